// round 13
// baseline (speedup 1.0000x reference)
#include <cuda_runtime.h>
#include <cuda_fp16.h>

#define N_NODES 50000
#define N_EDGES 1600000

// ---------------- scratch (device globals; no allocation allowed) ----------
__device__ uint2  g_WnH[N_NODES * 16];    // projected node features fp16: node*16+q holds halves [4q..4q+3]
__device__ float4 g_dotS[N_NODES];        // a_s . Wn[n]  per head (fp32)
__device__ float4 g_dotR[N_NODES];        // a_r . Wn[n]  per head (fp32)
__device__ float4 g_norm[N_NODES];        // softmax denominator per head (excl. self edge)
__device__ float4 g_aggr[N_NODES * 16];   // weighted sum [N,64] (excl. self edge)
__device__ float4 g_ce4[16];              // c_e as float4: g_ce4[h*4+q] = c_h[4q..4q+3]

__device__ __forceinline__ void red_add_v4(float4* addr, float x, float y, float z, float w) {
    asm volatile("red.global.add.v4.f32 [%0], {%1, %2, %3, %4};"
                 :: "l"(addr), "f"(x), "f"(y), "f"(z), "f"(w) : "memory");
}
__device__ __forceinline__ void red_add_f32(float* addr, float v) {
    asm volatile("red.global.add.f32 [%0], %1;" :: "l"(addr), "f"(v) : "memory");
}

// ---------------- K2: tiled GEMM node projection + dots + zero + c_e --------
#define NSTR 68
__global__ void __launch_bounds__(256) k_node(const float* __restrict__ nodes,
                                              const float* __restrict__ W,
                                              const float* __restrict__ a,
                                              const float* __restrict__ We) {
    __shared__ __align__(16) float sW[64 * NSTR];
    __shared__ __align__(16) float sN[64 * NSTR];   // input tile, then output tile
    __shared__ float sA[192];

    int tid = threadIdx.x;
    int nb  = blockIdx.x * 64;

    if (blockIdx.x == 0 && tid < 64) {              // c_e fold (once)
        int h = tid >> 4, i = tid & 15;
        float acc = 0.f;
#pragma unroll
        for (int f = 0; f < 16; f++)
            acc += a[h * 48 + 32 + f] * We[h * 256 + f * 16 + i];
        ((float*)g_ce4)[tid] = acc;
    }

    float4 z4 = make_float4(0.f, 0.f, 0.f, 0.f);
#pragma unroll
    for (int g = tid; g < 1024; g += 256) {
        int row = g >> 4, q = g & 15;
        *(float4*)&sW[row * NSTR + q * 4] = ((const float4*)W)[g];
        int node = nb + row;
        *(float4*)&sN[row * NSTR + q * 4] =
            (node < N_NODES) ? ((const float4*)nodes)[(size_t)node * 16 + q] : z4;
        if (node < N_NODES) g_aggr[(size_t)node * 16 + q] = z4;
    }
    if (tid < 192) sA[tid] = a[tid];
    if (tid < 64 && nb + tid < N_NODES) g_norm[nb + tid] = z4;
    __syncthreads();

    int jg = tid & 15, ng = tid >> 4;
    float acc[4][4];
#pragma unroll
    for (int nn = 0; nn < 4; nn++)
#pragma unroll
        for (int jj = 0; jj < 4; jj++) acc[nn][jj] = 0.f;

#pragma unroll
    for (int iq = 0; iq < 16; iq++) {
        float4 wv[4], nv[4];
#pragma unroll
        for (int jj = 0; jj < 4; jj++)
            wv[jj] = *(const float4*)&sW[(jg + jj * 16) * NSTR + iq * 4];
#pragma unroll
        for (int nn = 0; nn < 4; nn++)
            nv[nn] = *(const float4*)&sN[(ng + nn * 16) * NSTR + iq * 4];
#pragma unroll
        for (int nn = 0; nn < 4; nn++)
#pragma unroll
            for (int jj = 0; jj < 4; jj++)
                acc[nn][jj] += nv[nn].x * wv[jj].x + nv[nn].y * wv[jj].y
                             + nv[nn].z * wv[jj].z + nv[nn].w * wv[jj].w;
    }
    __syncthreads();

#pragma unroll
    for (int nn = 0; nn < 4; nn++)
#pragma unroll
        for (int jj = 0; jj < 4; jj++)
            sN[(ng + nn * 16) * NSTR + (jg + jj * 16)] = acc[nn][jj];
    __syncthreads();

    // fp16 Wn store
#pragma unroll
    for (int g = tid; g < 1024; g += 256) {
        int row = g >> 4, q = g & 15;
        int node = nb + row;
        if (node < N_NODES) {
            float4 v = *(const float4*)&sN[row * NSTR + q * 4];
            __half2 h0 = __floats2half2_rn(v.x, v.y);
            __half2 h1 = __floats2half2_rn(v.z, v.w);
            uint2 pk;
            pk.x = *(unsigned*)&h0;
            pk.y = *(unsigned*)&h1;
            g_WnH[(size_t)node * 16 + q] = pk;
        }
    }

    // dots from fp32 smem tile: thread = (local node, head)
    {
        int n = tid >> 2, h = tid & 3;
        const float* row = &sN[n * NSTR + h * 16];
        float ds = 0.f, dr = 0.f;
#pragma unroll
        for (int f = 0; f < 16; f++) {
            ds += row[f] * sA[h * 48 + f];
            dr += row[f] * sA[h * 48 + 16 + f];
        }
        int node = nb + n;
        if (node < N_NODES) {
            ((float*)g_dotS)[(size_t)node * 4 + h] = ds;
            ((float*)g_dotR)[(size_t)node * 4 + h] = dr;
        }
    }
}

// ---------------- K3: fused edge pass, 16 edges/warp (8x ILP) ----------------
// 16 lanes per edge-slot; each 16-lane group handles 8 edges with strictly
// stage-batched loads: 8 independent latency chains in flight per group.
// 1.6M edges = 12,500 blocks * 8 warps * 16 edges exactly: no bounds checks.
#define EILP 8
__global__ void __launch_bounds__(256) k_edge(const float* __restrict__ edges,
                                              const int* __restrict__ recv,
                                              const int* __restrict__ send) {
    int lane = threadIdx.x & 31;
    int sub  = lane & 15;
    int h    = sub >> 2;
    int q    = sub & 3;
    int base = (blockIdx.x * 8 + (threadIdx.x >> 5)) * (2 * EILP) + (lane >> 4);

    float4 c4 = g_ce4[sub];
    const float* dSf = (const float*)g_dotS;
    const float* dRf = (const float*)g_dotR;

    // stage 1: all index loads
    int s[EILP], r[EILP];
#pragma unroll
    for (int k = 0; k < EILP; k++) {
        int e = base + 2 * k;
        s[k] = send[e];
        r[k] = recv[e];
    }

    // stage 2: all edge-feature loads + partial dots
    float p[EILP];
#pragma unroll
    for (int k = 0; k < EILP; k++) {
        float4 ef = ((const float4*)edges)[(size_t)(base + 2 * k) * 4 + q];
        p[k] = ef.x * c4.x + ef.y * c4.y + ef.z * c4.z + ef.w * c4.w;
    }
#pragma unroll
    for (int k = 0; k < EILP; k++) {
        p[k] += __shfl_xor_sync(0xffffffffu, p[k], 1, 4);
        p[k] += __shfl_xor_sync(0xffffffffu, p[k], 2, 4);
    }

    // stage 3: all dot loads (batched before use)
    float dsv[EILP], drv[EILP];
#pragma unroll
    for (int k = 0; k < EILP; k++) dsv[k] = dSf[(size_t)s[k] * 4 + h];
#pragma unroll
    for (int k = 0; k < EILP; k++) drv[k] = dRf[(size_t)r[k] * 4 + h];

    // stage 4: all Wn gathers (batched)
    uint2 pk[EILP];
#pragma unroll
    for (int k = 0; k < EILP; k++) pk[k] = g_WnH[(size_t)s[k] * 16 + sub];

    // stage 5: weights
    float w[EILP];
#pragma unroll
    for (int k = 0; k < EILP; k++) {
        float m = dsv[k] + drv[k] + p[k];
        w[k] = __expf(m > 0.f ? m : 0.01f * m);
    }

    // stage 6: reductions
#pragma unroll
    for (int k = 0; k < EILP; k++) {
        if (q == 0) red_add_f32((float*)&g_norm[r[k]] + h, w[k]);
        float2 va = __half22float2(*(__half2*)&pk[k].x);
        float2 vb = __half22float2(*(__half2*)&pk[k].y);
        red_add_v4(&g_aggr[(size_t)r[k] * 16 + sub],
                   va.x * w[k], va.y * w[k], vb.x * w[k], vb.y * w[k]);
    }
}

// ---------------- K4: self-edge + normalize + ELU + LayerNorm ----------------
__global__ void k_final(const float* __restrict__ scale,
                        const float* __restrict__ bias,
                        float* __restrict__ out) {
    int lane = threadIdx.x & 31;
    int sub  = lane & 15;
    int h    = sub >> 2;
    int node = (blockIdx.x * 8 + (threadIdx.x >> 5)) * 2 + (lane >> 4);

    float ms = ((const float*)g_dotS)[(size_t)node * 4 + h]
             + ((const float*)g_dotR)[(size_t)node * 4 + h];
    float ws = __expf(ms > 0.f ? ms : 0.01f * ms);

    uint2 pk = g_WnH[(size_t)node * 16 + sub];
    float2 va = __half22float2(*(__half2*)&pk.x);
    float2 vb = __half22float2(*(__half2*)&pk.y);

    float4 ag = g_aggr[(size_t)node * 16 + sub];
    float  nm = ((const float*)&g_norm[node])[h] + ws;
    float inv_nm = 1.0f / nm;

    float x0 = (ag.x + ws * va.x) * inv_nm;
    float x1 = (ag.y + ws * va.y) * inv_nm;
    float x2 = (ag.z + ws * vb.x) * inv_nm;
    float x3 = (ag.w + ws * vb.y) * inv_nm;
    float y0 = x0 > 0.f ? x0 : expm1f(x0);
    float y1 = x1 > 0.f ? x1 : expm1f(x1);
    float y2 = x2 > 0.f ? x2 : expm1f(x2);
    float y3 = x3 > 0.f ? x3 : expm1f(x3);

    float sum = y0 + y1 + y2 + y3;
#pragma unroll
    for (int m = 8; m >= 1; m >>= 1) sum += __shfl_xor_sync(0xffffffffu, sum, m, 16);
    float mean = sum * (1.0f / 64.0f);

    float d0 = y0 - mean, d1 = y1 - mean, d2 = y2 - mean, d3 = y3 - mean;
    float v = d0 * d0 + d1 * d1 + d2 * d2 + d3 * d3;
#pragma unroll
    for (int m = 8; m >= 1; m >>= 1) v += __shfl_xor_sync(0xffffffffu, v, m, 16);
    float inv = rsqrtf(v * (1.0f / 64.0f) + 1e-6f);

    float4 sc = ((const float4*)scale)[sub];
    float4 bi = ((const float4*)bias)[sub];
    float4 o;
    o.x = d0 * inv * sc.x + bi.x;
    o.y = d1 * inv * sc.y + bi.y;
    o.z = d2 * inv * sc.z + bi.z;
    o.w = d3 * inv * sc.w + bi.w;
    ((float4*)out)[(size_t)node * 16 + sub] = o;
}

// ---------------- launch -----------------------------------------------------
extern "C" void kernel_launch(void* const* d_in, const int* in_sizes, int n_in,
                              void* d_out, int out_size) {
    const float* nodes   = (const float*)d_in[0];
    const float* edges   = (const float*)d_in[1];
    const int*   recv    = (const int*)d_in[2];
    const int*   send    = (const int*)d_in[3];
    const float* W       = (const float*)d_in[4];
    const float* W_edge  = (const float*)d_in[5];
    const float* a       = (const float*)d_in[6];
    const float* ln_s    = (const float*)d_in[7];
    const float* ln_b    = (const float*)d_in[8];
    float* out = (float*)d_out;

    k_node<<<(N_NODES + 63) / 64, 256>>>(nodes, W, a, W_edge);  // 782 blocks
    k_edge<<<N_EDGES / 128, 256>>>(edges, recv, send);          // 12,500 blocks, 16 edges/warp
    k_final<<<N_NODES / 16, 256>>>(ln_s, ln_b, out);            // 3125 blocks, exact
}